// round 2
// baseline (speedup 1.0000x reference)
#include <cuda_runtime.h>
#include <cstdint>

#define DIM_ 4096
#define BM 128
#define BN 128
#define BK 16
#define TM 8
#define TN 8
#define LDP 132   // padded smem row stride (floats): breaks transpose-store bank conflicts, keeps 16B alignment

// 64 MB scratch for quantized intermediate y_tilde (allocation-free rule: static __device__)
__device__ float g_yt[(size_t)DIM_ * DIM_];

// C = A @ B' with quantize-epilogue option.
//   B_KMAJOR=true : C[i,j] = sum_k A[i,k] * B[j,k]   (GEMM1: y = x @ Pi^T)
//   B_KMAJOR=false: C[i,j] = sum_k A[i,k] * B[k,j]   (GEMM2: x~ = y~ @ Pi)
//   QUANT=true    : A := Ain (x), C := g_yt, epilogue quantizes to nearest codebook entry
//   QUANT=false   : A := g_yt,    C := Cout (d_out)
template<bool B_KMAJOR, bool QUANT>
__global__ __launch_bounds__(256, 2)
void gemm_q_kernel(const float* __restrict__ Ain,
                   const float* __restrict__ B,
                   const float* __restrict__ cb,
                   float* __restrict__ Cout)
{
    __shared__ float As[BK][LDP];
    __shared__ float Bs[BK][LDP];
    __shared__ float s_cb[16];
    __shared__ float s_bnd[16];

    const int tid = threadIdx.x;
    const float* A = QUANT ? Ain : (const float*)g_yt;
    float*       C = QUANT ? (float*)g_yt : Cout;

    if (QUANT) {
        if (tid < 16) s_cb[tid] = cb[tid];
        __syncthreads();
        if (tid < 15) s_bnd[tid] = 0.5f * (s_cb[tid] + s_cb[tid + 1]);
        // visibility to all threads guaranteed by the main-loop __syncthreads below
    }

    const int row0 = blockIdx.y * BM;
    const int col0 = blockIdx.x * BN;
    const int ty = tid >> 4;    // 0..15 -> 8-row strip
    const int tx = tid & 15;    // 0..15 -> 8-col strip

    float acc[TM][TN];
    #pragma unroll
    for (int m = 0; m < TM; ++m)
        #pragma unroll
        for (int n = 0; n < TN; ++n) acc[m][n] = 0.0f;

    // --- global-load index precompute ---
    // K-major tile load (A always; B in GEMM1): 128 rows x 16 k, 512 float4s, 2 per thread
    const int ar0 = tid >> 2;            // row within tile, load 0
    const int ar1 = ar0 + 64;            // row within tile, load 1
    const int ac  = (tid & 3) * 4;       // k offset (float4)
    // Row-major B tile load (GEMM2): 16 k-rows x 128 cols
    const int bk0 = tid >> 5;            // k row, load 0
    const int bk1 = bk0 + 8;             // k row, load 1
    const int bj  = (tid & 31) * 4;      // col offset (float4)

    // --- software pipeline: prefetch tile 0 into registers ---
    float4 a0, a1, b0, b1;
    {
        a0 = *(const float4*)(A + (size_t)(row0 + ar0) * DIM_ + ac);
        a1 = *(const float4*)(A + (size_t)(row0 + ar1) * DIM_ + ac);
        if (B_KMAJOR) {
            b0 = *(const float4*)(B + (size_t)(col0 + ar0) * DIM_ + ac);
            b1 = *(const float4*)(B + (size_t)(col0 + ar1) * DIM_ + ac);
        } else {
            b0 = *(const float4*)(B + (size_t)bk0 * DIM_ + col0 + bj);
            b1 = *(const float4*)(B + (size_t)bk1 * DIM_ + col0 + bj);
        }
    }

    const int NT = DIM_ / BK;   // 256 k-tiles
    for (int t = 0; t < NT; ++t) {
        __syncthreads();   // previous iteration's smem reads complete before overwrite
        // store prefetched tile to smem (A transposed to k-major rows)
        As[ac + 0][ar0] = a0.x; As[ac + 1][ar0] = a0.y;
        As[ac + 2][ar0] = a0.z; As[ac + 3][ar0] = a0.w;
        As[ac + 0][ar1] = a1.x; As[ac + 1][ar1] = a1.y;
        As[ac + 2][ar1] = a1.z; As[ac + 3][ar1] = a1.w;
        if (B_KMAJOR) {
            Bs[ac + 0][ar0] = b0.x; Bs[ac + 1][ar0] = b0.y;
            Bs[ac + 2][ar0] = b0.z; Bs[ac + 3][ar0] = b0.w;
            Bs[ac + 0][ar1] = b1.x; Bs[ac + 1][ar1] = b1.y;
            Bs[ac + 2][ar1] = b1.z; Bs[ac + 3][ar1] = b1.w;
        } else {
            *(float4*)&Bs[bk0][bj] = b0;
            *(float4*)&Bs[bk1][bj] = b1;
        }
        __syncthreads();

        // prefetch next tile (LDG latency overlaps with FFMA block below)
        if (t + 1 < NT) {
            const int k0 = (t + 1) * BK;
            a0 = *(const float4*)(A + (size_t)(row0 + ar0) * DIM_ + k0 + ac);
            a1 = *(const float4*)(A + (size_t)(row0 + ar1) * DIM_ + k0 + ac);
            if (B_KMAJOR) {
                b0 = *(const float4*)(B + (size_t)(col0 + ar0) * DIM_ + k0 + ac);
                b1 = *(const float4*)(B + (size_t)(col0 + ar1) * DIM_ + k0 + ac);
            } else {
                b0 = *(const float4*)(B + (size_t)(k0 + bk0) * DIM_ + col0 + bj);
                b1 = *(const float4*)(B + (size_t)(k0 + bk1) * DIM_ + col0 + bj);
            }
        }

        // compute 128x128x16 with 8x8 register micro-tiles
        #pragma unroll
        for (int kk = 0; kk < BK; ++kk) {
            float a[TM], b[TN];
            *(float4*)&a[0] = *(const float4*)&As[kk][ty * TM];
            *(float4*)&a[4] = *(const float4*)&As[kk][ty * TM + 4];
            *(float4*)&b[0] = *(const float4*)&Bs[kk][tx * TN];
            *(float4*)&b[4] = *(const float4*)&Bs[kk][tx * TN + 4];
            #pragma unroll
            for (int m = 0; m < TM; ++m)
                #pragma unroll
                for (int n = 0; n < TN; ++n)
                    acc[m][n] = fmaf(a[m], b[n], acc[m][n]);
        }
    }

    // --- epilogue: optional quantize, then vectorized store ---
    #pragma unroll
    for (int m = 0; m < TM; ++m) {
        const int row = row0 + ty * TM + m;
        float v[TN];
        #pragma unroll
        for (int n = 0; n < TN; ++n) {
            float y = acc[m][n];
            if (QUANT) {
                int idx = 0;
                #pragma unroll
                for (int j = 0; j < 15; ++j) idx += (y > s_bnd[j]) ? 1 : 0;
                y = s_cb[idx];
            }
            v[n] = y;
        }
        float* cp = C + (size_t)row * DIM_ + col0 + tx * TN;
        *(float4*)(cp + 0) = make_float4(v[0], v[1], v[2], v[3]);
        *(float4*)(cp + 4) = make_float4(v[4], v[5], v[6], v[7]);
    }
}

extern "C" void kernel_launch(void* const* d_in, const int* in_sizes, int n_in,
                              void* d_out, int out_size)
{
    const float* x  = (const float*)d_in[0];   // (N_TOKENS, DIM)
    const float* Pi = (const float*)d_in[1];   // (DIM, DIM)
    const float* cb = (const float*)d_in[2];   // (16,)
    float* out = (float*)d_out;

    const int M = in_sizes[0] / DIM_;          // N_TOKENS = 4096

    dim3 blk(256);
    dim3 grid(DIM_ / BN, M / BM);

    // GEMM1 + quantize: g_yt = Q(x @ Pi^T)
    gemm_q_kernel<true, true><<<grid, blk>>>(x, Pi, cb, out);
    // GEMM2: out = g_yt @ Pi
    gemm_q_kernel<false, false><<<grid, blk>>>(x, Pi, cb, out);
}

// round 5
// speedup vs baseline: 3.6562x; 3.6562x over previous
#include <cuda_runtime.h>
#include <cuda_bf16.h>
#include <cstdint>

#define DIM_ 4096
#define BM 128
#define BN 128
#define BKH 32               // bf16 k per chunk (64B of data per row)
#define NCH (DIM_ / BKH)     // 128 chunks
#define ROWB 80              // padded smem row stride in bytes (64B data + 16B pad)
#define TILEB (BM * ROWB)    // 10240 B per tile
#define STGB (4 * TILEB)     // 4 tiles per stage (A0,A1,B0,B1)
#define NSTG 3

// ---------------- scratch (allocation-free rule: __device__ globals) --------
__device__ unsigned short g_x0[(size_t)DIM_ * DIM_];
__device__ unsigned short g_x1[(size_t)DIM_ * DIM_];
__device__ unsigned short g_p0[(size_t)DIM_ * DIM_];   // Pi splits (K-major rows)
__device__ unsigned short g_p1[(size_t)DIM_ * DIM_];
__device__ unsigned short g_t0[(size_t)DIM_ * DIM_];   // Pi^T splits (K-major rows)
__device__ unsigned short g_t1[(size_t)DIM_ * DIM_];
__device__ unsigned short g_y0[(size_t)DIM_ * DIM_];   // quantized y split hi
__device__ unsigned short g_y1[(size_t)DIM_ * DIM_];   // quantized y split lo

// ---------------- PTX helpers (all legal at compute_103) --------------------
__device__ __forceinline__ uint32_t smem_u32(const void* p) {
    uint32_t a;
    asm("{ .reg .u64 t; cvta.to.shared.u64 t, %1; cvt.u32.u64 %0, t; }" : "=r"(a) : "l"(p));
    return a;
}
__device__ __forceinline__ void cpasync16(uint32_t sa, const void* g) {
    asm volatile("cp.async.cg.shared.global [%0], [%1], 16;" :: "r"(sa), "l"(g));
}
__device__ __forceinline__ void ldsm4(uint32_t* r, uint32_t a) {
    asm volatile("ldmatrix.sync.aligned.m8n8.x4.shared.b16 {%0,%1,%2,%3}, [%4];"
                 : "=r"(r[0]), "=r"(r[1]), "=r"(r[2]), "=r"(r[3]) : "r"(a));
}
__device__ __forceinline__ void mma16816(float* d, const uint32_t* a, const uint32_t* b) {
    asm volatile("mma.sync.aligned.m16n8k16.row.col.f32.bf16.bf16.f32 "
                 "{%0,%1,%2,%3}, {%4,%5,%6,%7}, {%8,%9}, {%0,%1,%2,%3};"
                 : "+f"(d[0]), "+f"(d[1]), "+f"(d[2]), "+f"(d[3])
                 : "r"(a[0]), "r"(a[1]), "r"(a[2]), "r"(a[3]), "r"(b[0]), "r"(b[1]));
}
#define CP_COMMIT() asm volatile("cp.async.commit_group;" ::: "memory")
#define CP_WAIT1()  asm volatile("cp.async.wait_group 1;" ::: "memory")

// ---------------- split preprocessing ---------------------------------------
__device__ __forceinline__ void bsplit2(float v, unsigned short& b0, unsigned short& b1) {
    __nv_bfloat16 h0 = __float2bfloat16(v);
    float r = v - __bfloat162float(h0);
    __nv_bfloat16 h1 = __float2bfloat16(r);
    b0 = *reinterpret_cast<unsigned short*>(&h0);
    b1 = *reinterpret_cast<unsigned short*>(&h1);
}

__global__ void split2_kernel(const float4* __restrict__ in,
                              uint32_t* __restrict__ o0, uint32_t* __restrict__ o1) {
    int i = blockIdx.x * blockDim.x + threadIdx.x;   // one float4 per thread
    float4 v = in[i];
    unsigned short a0[4], a1[4];
    bsplit2(v.x, a0[0], a1[0]);
    bsplit2(v.y, a0[1], a1[1]);
    bsplit2(v.z, a0[2], a1[2]);
    bsplit2(v.w, a0[3], a1[3]);
    o0[2 * i] = a0[0] | ((uint32_t)a0[1] << 16); o0[2 * i + 1] = a0[2] | ((uint32_t)a0[3] << 16);
    o1[2 * i] = a1[0] | ((uint32_t)a1[1] << 16); o1[2 * i + 1] = a1[2] | ((uint32_t)a1[3] << 16);
}

__global__ void transsplit2_kernel(const float* __restrict__ Pi,
                                   unsigned short* __restrict__ t0,
                                   unsigned short* __restrict__ t1) {
    __shared__ float tile[32][33];
    int tx = threadIdx.x, ty = threadIdx.y;
    int c0 = blockIdx.x * 32, r0 = blockIdx.y * 32;
    #pragma unroll
    for (int i = 0; i < 4; ++i)
        tile[ty + 8 * i][tx] = Pi[(size_t)(r0 + ty + 8 * i) * DIM_ + c0 + tx];
    __syncthreads();
    #pragma unroll
    for (int i = 0; i < 4; ++i) {
        float v = tile[tx][ty + 8 * i];
        unsigned short b0, b1;
        bsplit2(v, b0, b1);
        size_t o = (size_t)(c0 + ty + 8 * i) * DIM_ + r0 + tx;
        t0[o] = b0;
        t1[o] = b1;
    }
}

// ---------------- split GEMM via mma.sync (HMMA) ----------------------------
// C[i,j] = sum_k A0*B0 + A0*B1 + A1*B0   (a1*b1 dropped: below noise floor)
// All operands K-major. QUANT: quantize epilogue -> (Y0,Y1) bf16 split pair.
template<bool QUANT>
__global__ __launch_bounds__(256, 1)
void hmma_gemm(const unsigned short* __restrict__ A0, const unsigned short* __restrict__ A1,
               const unsigned short* __restrict__ Bm0, const unsigned short* __restrict__ Bm1,
               const float* __restrict__ cb, float* __restrict__ Cout,
               unsigned short* __restrict__ Y0, unsigned short* __restrict__ Y1)
{
    extern __shared__ char smem[];
    const uint32_t sb = smem_u32(smem);
    __shared__ float s_bnd[15];
    __shared__ uint32_t s_cbp[16];

    const int tid = threadIdx.x;
    const int w = tid >> 5, l = tid & 31;
    const int wm = w & 3, wn = w >> 2;          // 4x2 warp grid, warp tile 32x64
    const int row0 = blockIdx.y * BM;
    const int col0 = blockIdx.x * BN;

    if (QUANT) {
        if (tid < 16) {
            float c = cb[tid];
            unsigned short b0, b1;
            bsplit2(c, b0, b1);
            s_cbp[tid] = (uint32_t)b0 | ((uint32_t)b1 << 16);
        }
        if (tid < 15) s_bnd[tid] = 0.5f * (cb[tid] + cb[tid + 1]);
        // visibility: first main-loop __syncthreads
    }

    const unsigned short* srcs[4] = {A0, A1, Bm0, Bm1};
    const int rb[4] = {row0, row0, col0, col0};

    auto load_chunk = [&](int ch, int st) {
        const int k0 = ch * BKH;
        const uint32_t stg = sb + st * STGB;
        #pragma unroll
        for (int t = 0; t < 4; ++t) {
            #pragma unroll
            for (int i = 0; i < 2; ++i) {
                int id = i * 256 + tid;          // 512 x 16B chunks per tile
                int r = id >> 2, c = id & 3;
                const void* g = srcs[t] + (size_t)(rb[t] + r) * DIM_ + k0 + c * 8;
                cpasync16(stg + t * TILEB + r * ROWB + c * 16, g);
            }
        }
        CP_COMMIT();
    };

    float acc[2][8][4];
    #pragma unroll
    for (int f = 0; f < 2; ++f)
        #pragma unroll
        for (int j = 0; j < 8; ++j)
            #pragma unroll
            for (int q = 0; q < 4; ++q) acc[f][j][q] = 0.0f;

    // lane-invariant fragment offsets (bytes within a tile)
    const uint32_t a_off = (uint32_t)(wm * 32 + (l & 15)) * ROWB + (l >> 4) * 16;
    const uint32_t b_off = (uint32_t)(wn * 64 + (l & 7) + ((l >> 4) & 1) * 8) * ROWB
                         + ((l >> 3) & 1) * 16;

    load_chunk(0, 0);
    load_chunk(1, 1);

    for (int t = 0; t < NCH; ++t) {
        const int st = t % NSTG;
        CP_WAIT1();
        __syncthreads();
        if (t + 2 < NCH) load_chunk(t + 2, (t + 2) % NSTG);

        const uint32_t base = sb + st * STGB;
        #pragma unroll
        for (int ks = 0; ks < 2; ++ks) {
            uint32_t afr[2][2][4];              // [split][mfrag][4]
            #pragma unroll
            for (int s = 0; s < 2; ++s)
                #pragma unroll
                for (int f = 0; f < 2; ++f)
                    ldsm4(afr[s][f], base + s * TILEB + a_off + f * 16 * ROWB + ks * 32);

            #pragma unroll
            for (int sB = 0; sB < 2; ++sB) {
                uint32_t bfr[4][4];             // 8 n-frags of (16x8)
                #pragma unroll
                for (int p = 0; p < 4; ++p)
                    ldsm4(bfr[p], base + (2 + sB) * TILEB + b_off + p * 16 * ROWB + ks * 32);
                // pairs: sB==0 -> a0*b0, a1*b0 ; sB==1 -> a0*b1
                #pragma unroll
                for (int f = 0; f < 2; ++f)
                    #pragma unroll
                    for (int j = 0; j < 8; ++j)
                        mma16816(acc[f][j], afr[0][f], &bfr[j >> 1][(j & 1) * 2]);
                if (sB == 0) {
                    #pragma unroll
                    for (int f = 0; f < 2; ++f)
                        #pragma unroll
                        for (int j = 0; j < 8; ++j)
                            mma16816(acc[f][j], afr[1][f], &bfr[j >> 1][(j & 1) * 2]);
                }
            }
        }
    }

    // ---- register epilogue --------------------------------------------------
    // acc[f][j][q]: (m = wm*32 + f*16 + (q>=2)*8 + l/4, n = wn*64 + j*8 + 2*(l&3) + (q&1))
    #pragma unroll
    for (int f = 0; f < 2; ++f) {
        #pragma unroll
        for (int j = 0; j < 8; ++j) {
            const int nb = col0 + wn * 64 + j * 8 + (l & 3) * 2;
            #pragma unroll
            for (int h = 0; h < 2; ++h) {
                const int row = row0 + wm * 32 + f * 16 + h * 8 + (l >> 2);
                const float va = acc[f][j][2 * h];
                const float vb = acc[f][j][2 * h + 1];
                if (QUANT) {
                    int ia = 0, ib = 0;
                    #pragma unroll
                    for (int q = 0; q < 15; ++q) {
                        ia += (va > s_bnd[q]) ? 1 : 0;
                        ib += (vb > s_bnd[q]) ? 1 : 0;
                    }
                    const uint32_t qa = s_cbp[ia], qb = s_cbp[ib];
                    const size_t o = ((size_t)row * DIM_ + nb) >> 1;   // u32 index
                    ((uint32_t*)Y0)[o] = (qa & 0xFFFFu) | (qb << 16);
                    ((uint32_t*)Y1)[o] = (qa >> 16) | (qb & 0xFFFF0000u);
                } else {
                    float2 v2 = make_float2(va, vb);
                    *(float2*)(Cout + (size_t)row * DIM_ + nb) = v2;
                }
            }
        }
    }
}

// ---------------- host ------------------------------------------------------
extern "C" void kernel_launch(void* const* d_in, const int* in_sizes, int n_in,
                              void* d_out, int out_size)
{
    const float* x  = (const float*)d_in[0];
    const float* Pi = (const float*)d_in[1];
    const float* cb = (const float*)d_in[2];
    float* out = (float*)d_out;

    unsigned short *x0, *x1, *p0, *p1, *t0, *t1, *y0, *y1;
    cudaGetSymbolAddress((void**)&x0, g_x0);
    cudaGetSymbolAddress((void**)&x1, g_x1);
    cudaGetSymbolAddress((void**)&p0, g_p0);
    cudaGetSymbolAddress((void**)&p1, g_p1);
    cudaGetSymbolAddress((void**)&t0, g_t0);
    cudaGetSymbolAddress((void**)&t1, g_t1);
    cudaGetSymbolAddress((void**)&y0, g_y0);
    cudaGetSymbolAddress((void**)&y1, g_y1);

    const size_t N = (size_t)DIM_ * DIM_;
    const int smem = NSTG * STGB;   // 122880 B
    cudaFuncSetAttribute(hmma_gemm<true>,
                         cudaFuncAttributeMaxDynamicSharedMemorySize, smem);
    cudaFuncSetAttribute(hmma_gemm<false>,
                         cudaFuncAttributeMaxDynamicSharedMemorySize, smem);

    // 1) splits: x -> (x0,x1), Pi -> (p0,p1), Pi^T -> (t0,t1)
    split2_kernel<<<(int)(N / 4 / 256), 256>>>((const float4*)x, (uint32_t*)x0, (uint32_t*)x1);
    split2_kernel<<<(int)(N / 4 / 256), 256>>>((const float4*)Pi, (uint32_t*)p0, (uint32_t*)p1);
    transsplit2_kernel<<<dim3(DIM_ / 32, DIM_ / 32), dim3(32, 8)>>>(Pi, t0, t1);

    dim3 grid(DIM_ / BN, DIM_ / BM);
    // 2) GEMM1 + quantize: (y0,y1) = split(Q(x @ Pi^T))
    hmma_gemm<true><<<grid, 256, smem>>>(x0, x1, p0, p1, cb, nullptr, y0, y1);
    // 3) GEMM2: out = y~ @ Pi   (B operand = Pi^T splits, K-major)
    hmma_gemm<false><<<grid, 256, smem>>>(y0, y1, t0, t1, nullptr, out, nullptr, nullptr);
}